// round 4
// baseline (speedup 1.0000x reference)
#include <cuda_runtime.h>
#include <cuda_fp16.h>
#include <math.h>

#define NG        2048
#define IMG_H     128
#define IMG_W     128
#define TILE_W    16
#define TILE_H    8
#define TILES_X   (IMG_W / TILE_W)    // 8
#define TILES_Y   (IMG_H / TILE_H)    // 16
#define NTILES    (TILES_X * TILES_Y) // 128
#define TPB       128                 // threads per rasterize block (= tile px)
#define NEAR_P    0.3f
#define EPS_C     1e-4f
#define INV_FOCAL (1.0f / 128.0f)
#define UNORM_INV (1.0f / 65535.0f)
// -0.5 * log2(e): folds exp(-0.5*qf) -> exp2(K*qf) with K baked into ia/ib/ic
#define NEG_HALF_LOG2E (-0.72134752044448170368f)

// ---------------- static scratch (no dynamic allocation allowed) -------------
// Packed per-gaussian payload (32B):
//  A = (u, v, ia*K, ib*K)         K = -0.5*log2(e)
//  B = (ic*K, bitcast(half2(rx,ry)), bitcast(unorm16 r|g), bitcast(unorm16 b|opa))
__device__ float4 dA[NG], dB[NG];               // unsorted
__device__ float4 gA[NG + TPB], gB[NG + TPB];   // depth-sorted (+zero pad for prefetch)

union F2H2 { __half2 h; float f; unsigned u; };

__device__ __forceinline__ float ex2_approx(float x) {
    float r;
    asm("ex2.approx.f32 %0, %1;" : "=f"(r) : "f"(x));
    return r;
}

// ---------------- 1. fused preprocess + bitonic depth-argsort + gather -------
__global__ void __launch_bounds__(1024) prep_sort_kernel(
        const float* __restrict__ pos,
        const float* __restrict__ rgb,
        const float* __restrict__ opa,
        const float* __restrict__ quat,
        const float* __restrict__ scale,
        const float* __restrict__ rot,
        const float* __restrict__ tran) {
    __shared__ unsigned long long sk[NG];   // (depth bits << 32) | index
    int tid = threadIdx.x;

    float R00 = rot[0], R01 = rot[1], R02 = rot[2];
    float R10 = rot[3], R11 = rot[4], R12 = rot[5];
    float R20 = rot[6], R21 = rot[7], R22 = rot[8];
    float t0 = tran[0], t1 = tran[1], t2 = tran[2];

    // ---- phase 1: preprocess 2 gaussians per thread ----
    for (int i = tid; i < NG; i += 1024) {
        float px = pos[3*i+0], py = pos[3*i+1], pz = pos[3*i+2];
        float x = R00*px + R01*py + R02*pz + t0;
        float y = R10*px + R11*py + R12*pz + t1;
        float z = R20*px + R21*py + R22*pz + t2;

        float r  = sqrtf(x*x + y*y + z*z);
        float iz = 1.0f / z;
        float u  = x * iz, v = y * iz;
        float iz2 = iz * iz;

        // JW rows 0,1 (J @ rot); row 2 not needed for the 2x2 cov block
        float J00 = iz*R00 - x*iz2*R20;
        float J01 = iz*R01 - x*iz2*R21;
        float J02 = iz*R02 - x*iz2*R22;
        float J10 = iz*R10 - y*iz2*R20;
        float J11 = iz*R11 - y*iz2*R21;
        float J12 = iz*R12 - y*iz2*R22;

        float qw = quat[4*i+0], qx = quat[4*i+1], qy = quat[4*i+2], qz = quat[4*i+3];
        float qn = rsqrtf(qw*qw + qx*qx + qy*qy + qz*qz);
        qw *= qn; qx *= qn; qy *= qn; qz *= qn;
        float m00 = 1.f - 2.f*(qy*qy + qz*qz);
        float m01 = 2.f*(qx*qy - qw*qz);
        float m02 = 2.f*(qx*qz + qw*qy);
        float m10 = 2.f*(qx*qy + qw*qz);
        float m11 = 1.f - 2.f*(qx*qx + qz*qz);
        float m12 = 2.f*(qy*qz - qw*qx);
        float m20 = 2.f*(qx*qz - qw*qy);
        float m21 = 2.f*(qy*qz + qw*qx);
        float m22 = 1.f - 2.f*(qx*qx + qy*qy);

        float s0 = fabsf(scale[3*i+0]) + EPS_C;
        float s1 = fabsf(scale[3*i+1]) + EPS_C;
        float s2 = fabsf(scale[3*i+2]) + EPS_C;

        float a00 = m00*s0, a01 = m01*s1, a02 = m02*s2;
        float a10 = m10*s0, a11 = m11*s1, a12 = m12*s2;
        float a20 = m20*s0, a21 = m21*s1, a22 = m22*s2;

        float C00 = a00*a00 + a01*a01 + a02*a02;
        float C01 = a00*a10 + a01*a11 + a02*a12;
        float C02 = a00*a20 + a01*a21 + a02*a22;
        float C11 = a10*a10 + a11*a11 + a12*a12;
        float C12 = a10*a20 + a11*a21 + a12*a22;
        float C22 = a20*a20 + a21*a21 + a22*a22;

        float u0x = C00*J00 + C01*J01 + C02*J02;
        float u0y = C01*J00 + C11*J01 + C12*J02;
        float u0z = C02*J00 + C12*J01 + C22*J02;
        float a = J00*u0x + J01*u0y + J02*u0z + 1e-4f;
        float b = J10*u0x + J11*u0y + J12*u0z;
        float u1x = C00*J10 + C01*J11 + C02*J12;
        float u1y = C01*J10 + C11*J11 + C12*J12;
        float u1z = C02*J10 + C12*J11 + C22*J12;
        float c = J10*u1x + J11*u1y + J12*u1z + 1e-4f;

        float det  = a*c - b*b;
        float idet = 1.0f / det;
        // fold -0.5*log2(e) so rasterize does al = opa * exp2(quadform')
        float ia =  c * idet * NEG_HALF_LOG2E;
        float ib = -b * idet * NEG_HALF_LOG2E;
        float ic =  a * idet * NEG_HALF_LOG2E;

        float opa_s = 1.0f / (1.0f + __expf(-opa[i]));
        float oeff  = (z > NEAR_P) ? opa_s : 0.0f;

        // cull ellipse: contribution outside <= e^-20: Q = 2*(20+ln(opa))
        // (computed from UNscaled a, c in natural-log space)
        float Q  = 2.0f * (20.0f + __logf(fmaxf(oeff, 1e-30f)));
        float rx = (Q > 0.0f) ? sqrtf(Q * a) * 1.001f : -1.0f;  // 1.001: half-round pad
        float ry = (Q > 0.0f) ? sqrtf(Q * c) * 1.001f : -1.0f;

        float sr = 1.0f / (1.0f + __expf(-rgb[3*i+0]));
        float sg = 1.0f / (1.0f + __expf(-rgb[3*i+1]));
        float sb = 1.0f / (1.0f + __expf(-rgb[3*i+2]));

        F2H2 hh; hh.h = __floats2half2_rn(rx, ry);
        unsigned lo = (unsigned)__float2uint_rn(sr * 65535.0f)
                    | ((unsigned)__float2uint_rn(sg * 65535.0f) << 16);
        unsigned hi = (unsigned)__float2uint_rn(sb * 65535.0f)
                    | ((unsigned)__float2uint_rn(oeff * 65535.0f) << 16);

        dA[i] = make_float4(u, v, ia, ib);
        dB[i] = make_float4(ic, hh.f, __uint_as_float(lo), __uint_as_float(hi));
        sk[i] = ((unsigned long long)__float_as_uint(r) << 32) | (unsigned)i;
    }
    __syncthreads();   // block-scope fence: dA/dB visible block-wide

    // ---- phase 2: bitonic sort of packed (key|idx) in shared ----
    for (int k = 2; k <= NG; k <<= 1) {
        for (int j = k >> 1; j > 0; j >>= 1) {
            #pragma unroll 1
            for (int t = tid; t < NG; t += 1024) {
                int ixj = t ^ j;
                if (ixj > t) {
                    bool up = ((t & k) == 0);
                    unsigned long long v0 = sk[t], v1 = sk[ixj];
                    if ((v0 > v1) == up) { sk[t] = v1; sk[ixj] = v0; }
                }
            }
            __syncthreads();
        }
    }

    // ---- phase 3: gather into depth order ----
    for (int t = tid; t < NG; t += 1024) {
        int o = (int)(sk[t] & 0xffffffffu);
        gA[t] = dA[o];
        gB[t] = dB[o];
    }
}

// ---------------- 2. fused tile cull + front-to-back compositing --------------
__global__ void __launch_bounds__(TPB) rasterize_kernel(float* __restrict__ out) {
    int tile = blockIdx.x;            // 128 blocks x 128 threads (1 px/thread)
    int tid  = threadIdx.x;
    int wid  = tid >> 5, lane = tid & 31;
    int tx = tile % TILES_X, ty = tile / TILES_X;
    int lx = tid & (TILE_W - 1), ly = tid >> 4;
    int j = tx * TILE_W + lx;         // column
    int i = ty * TILE_H + ly;         // row
    float pxf = ((float)j - 63.5f) * INV_FOCAL;
    float pyf = ((float)i - 63.5f) * INV_FOCAL;

    // tile bounds (pixel centers)
    float x0 = ((float)(tx * TILE_W) - 63.5f) * INV_FOCAL;
    float x1 = ((float)(tx * TILE_W + TILE_W - 1) - 63.5f) * INV_FOCAL;
    float y0 = ((float)(ty * TILE_H) - 63.5f) * INV_FOCAL;
    float y1 = ((float)(ty * TILE_H + TILE_H - 1) - 63.5f) * INV_FOCAL;

    __shared__ float4 shA[TPB];       // u, v, ia', ib'
    __shared__ float2 shB[TPB];       // ic', opa
    __shared__ float4 shC[TPB];       // r, g, b
    __shared__ int    wcnt[4];

    float T = 1.0f, cr = 0.0f, cg = 0.0f, cb = 0.0f;

    float4 A = gA[tid];               // chunk-0 prefetch
    float4 B = gB[tid];

    for (int k0 = 0; k0 < NG; k0 += TPB) {
        // prefetch next chunk (pad region is zero => safe, unused on exit)
        float4 An = gA[k0 + TPB + tid];
        float4 Bn = gB[k0 + TPB + tid];

        // bbox test
        F2H2 hh; hh.f = B.y;
        float2 rr = __half22float2(hh.h);
        bool hit = (rr.x > 0.0f) &&
                   (A.x + rr.x >= x0) && (A.x - rr.x <= x1) &&
                   (A.y + rr.y >= y0) && (A.y - rr.y <= y1);

        unsigned m = __ballot_sync(0xffffffffu, hit);
        if (lane == 0) wcnt[wid] = __popc(m);
        __syncthreads();

        int base = 0, mm = 0;
        #pragma unroll
        for (int w = 0; w < 4; w++) {
            int c = wcnt[w];
            if (w < wid) base += c;
            mm += c;
        }
        if (hit) {
            int off = base + __popc(m & ((1u << lane) - 1u));
            unsigned lo = __float_as_uint(B.z), hi = __float_as_uint(B.w);
            shA[off] = A;
            shB[off] = make_float2(B.x, (float)(hi >> 16) * UNORM_INV);
            shC[off] = make_float4((float)(lo & 0xffffu) * UNORM_INV,
                                   (float)(lo >> 16)     * UNORM_INV,
                                   (float)(hi & 0xffffu) * UNORM_INV, 0.0f);
        }
        __syncthreads();

        #pragma unroll 4
        for (int t = 0; t < mm; t++) {
            float4 Ai = shA[t];
            float2 Bi = shB[t];
            float4 Ci = shC[t];
            float dx = pxf - Ai.x;
            float dy = pyf - Ai.y;
            float e1 = fmaf(Ai.z, dx, Ai.w * dy);
            float e2 = fmaf(Ai.w, dx, Bi.x * dy);
            float qf = fmaf(dx, e1, dy * e2);     // already -0.5*log2e * quadform
            float al = fminf(Bi.y * ex2_approx(qf), 0.99f);
            float w  = T * al;
            cr = fmaf(w, Ci.x, cr);
            cg = fmaf(w, Ci.y, cg);
            cb = fmaf(w, Ci.z, cb);
            T  = fmaf(-al, T, T);
        }
        // guards shared reuse AND gives block-uniform early exit when opaque
        if (__syncthreads_and(T < 1e-7f)) break;

        A = An; B = Bn;
    }

    int p = i * IMG_W + j;
    out[3*p+0] = cr;
    out[3*p+1] = cg;
    out[3*p+2] = cb;
}

// ---------------- launch -----------------------------------------------------
extern "C" void kernel_launch(void* const* d_in, const int* in_sizes, int n_in,
                              void* d_out, int out_size) {
    const float* pos   = (const float*)d_in[0];
    const float* rgb   = (const float*)d_in[1];
    const float* opa   = (const float*)d_in[2];
    const float* quat  = (const float*)d_in[3];
    const float* scale = (const float*)d_in[4];
    const float* rot   = (const float*)d_in[5];
    const float* tran  = (const float*)d_in[6];
    float* out = (float*)d_out;

    prep_sort_kernel<<<1, 1024>>>(pos, rgb, opa, quat, scale, rot, tran);
    rasterize_kernel<<<NTILES, TPB>>>(out);
}

// round 5
// speedup vs baseline: 2.2650x; 2.2650x over previous
#include <cuda_runtime.h>
#include <cuda_fp16.h>
#include <math.h>

#define NG        2048
#define IMG_H     128
#define IMG_W     128
#define NPIX      (IMG_H * IMG_W)
#define TILE_W    16
#define TILE_H    8
#define TILES_X   (IMG_W / TILE_W)    // 8
#define TILES_Y   (IMG_H / TILE_H)    // 16
#define NTILES    (TILES_X * TILES_Y) // 128
#define TPB       128                 // threads per rasterize block (= tile px)
#define NSPLIT    4                   // depth-range splits per tile
#define SPLIT_LEN (NG / NSPLIT)       // 512 gaussians per split
#define NEAR_P    0.3f
#define EPS_C     1e-4f
#define INV_FOCAL (1.0f / 128.0f)
#define UNORM_INV (1.0f / 65535.0f)
// -0.5 * log2(e): folds exp(-0.5*qf) -> exp2(K*qf) with K baked into ia/ib/ic
#define NEG_HALF_LOG2E (-0.72134752044448170368f)

// ---------------- static scratch (no dynamic allocation allowed) -------------
// Packed per-gaussian payload (32B):
//  A = (u, v, ia*K, ib*K)         K = -0.5*log2(e)
//  B = (ic*K, bitcast(half2(rx,ry)), bitcast(unorm16 r|g), bitcast(unorm16 b|opa))
__device__ float4 dA[NG], dB[NG];               // unsorted
__device__ float4 gA[NG + TPB], gB[NG + TPB];   // depth-sorted (+zero pad: never written)
__device__ unsigned long long dKey[NG];         // (depth bits << 32) | index
__device__ float4 dPart[NSPLIT][NPIX];          // split partials (r,g,b,T)

union F2H2 { __half2 h; float f; unsigned u; };

__device__ __forceinline__ float ex2_approx(float x) {
    float r;
    asm("ex2.approx.f32 %0, %1;" : "=f"(r) : "f"(x));
    return r;
}

// ---------------- 1. per-gaussian preprocess (full chip) ---------------------
__global__ void __launch_bounds__(128) prep_kernel(
        const float* __restrict__ pos,
        const float* __restrict__ rgb,
        const float* __restrict__ opa,
        const float* __restrict__ quat,
        const float* __restrict__ scale,
        const float* __restrict__ rot,
        const float* __restrict__ tran) {
    int i = blockIdx.x * blockDim.x + threadIdx.x;
    if (i >= NG) return;

    float R00 = rot[0], R01 = rot[1], R02 = rot[2];
    float R10 = rot[3], R11 = rot[4], R12 = rot[5];
    float R20 = rot[6], R21 = rot[7], R22 = rot[8];

    float px = pos[3*i+0], py = pos[3*i+1], pz = pos[3*i+2];
    float x = R00*px + R01*py + R02*pz + tran[0];
    float y = R10*px + R11*py + R12*pz + tran[1];
    float z = R20*px + R21*py + R22*pz + tran[2];

    float r  = sqrtf(x*x + y*y + z*z);
    float iz = 1.0f / z;
    float u  = x * iz, v = y * iz;
    float iz2 = iz * iz;

    // JW rows 0,1 (J @ rot); row 2 not needed for the 2x2 cov block
    float J00 = iz*R00 - x*iz2*R20;
    float J01 = iz*R01 - x*iz2*R21;
    float J02 = iz*R02 - x*iz2*R22;
    float J10 = iz*R10 - y*iz2*R20;
    float J11 = iz*R11 - y*iz2*R21;
    float J12 = iz*R12 - y*iz2*R22;

    float qw = quat[4*i+0], qx = quat[4*i+1], qy = quat[4*i+2], qz = quat[4*i+3];
    float qn = rsqrtf(qw*qw + qx*qx + qy*qy + qz*qz);
    qw *= qn; qx *= qn; qy *= qn; qz *= qn;
    float m00 = 1.f - 2.f*(qy*qy + qz*qz);
    float m01 = 2.f*(qx*qy - qw*qz);
    float m02 = 2.f*(qx*qz + qw*qy);
    float m10 = 2.f*(qx*qy + qw*qz);
    float m11 = 1.f - 2.f*(qx*qx + qz*qz);
    float m12 = 2.f*(qy*qz - qw*qx);
    float m20 = 2.f*(qx*qz - qw*qy);
    float m21 = 2.f*(qy*qz + qw*qx);
    float m22 = 1.f - 2.f*(qx*qx + qy*qy);

    float s0 = fabsf(scale[3*i+0]) + EPS_C;
    float s1 = fabsf(scale[3*i+1]) + EPS_C;
    float s2 = fabsf(scale[3*i+2]) + EPS_C;

    float a00 = m00*s0, a01 = m01*s1, a02 = m02*s2;
    float a10 = m10*s0, a11 = m11*s1, a12 = m12*s2;
    float a20 = m20*s0, a21 = m21*s1, a22 = m22*s2;

    float C00 = a00*a00 + a01*a01 + a02*a02;
    float C01 = a00*a10 + a01*a11 + a02*a12;
    float C02 = a00*a20 + a01*a21 + a02*a22;
    float C11 = a10*a10 + a11*a11 + a12*a12;
    float C12 = a10*a20 + a11*a21 + a12*a22;
    float C22 = a20*a20 + a21*a21 + a22*a22;

    float u0x = C00*J00 + C01*J01 + C02*J02;
    float u0y = C01*J00 + C11*J01 + C12*J02;
    float u0z = C02*J00 + C12*J01 + C22*J02;
    float a = J00*u0x + J01*u0y + J02*u0z + 1e-4f;
    float b = J10*u0x + J11*u0y + J12*u0z;
    float u1x = C00*J10 + C01*J11 + C02*J12;
    float u1y = C01*J10 + C11*J11 + C12*J12;
    float u1z = C02*J10 + C12*J11 + C22*J12;
    float c = J10*u1x + J11*u1y + J12*u1z + 1e-4f;

    float det  = a*c - b*b;
    float idet = 1.0f / det;
    float ia =  c * idet * NEG_HALF_LOG2E;   // fold exp2 scale into quad form
    float ib = -b * idet * NEG_HALF_LOG2E;
    float ic =  a * idet * NEG_HALF_LOG2E;

    float opa_s = 1.0f / (1.0f + __expf(-opa[i]));
    float oeff  = (z > NEAR_P) ? opa_s : 0.0f;

    // cull ellipse: contribution outside <= e^-20: Q = 2*(20+ln(opa))
    float Q  = 2.0f * (20.0f + __logf(fmaxf(oeff, 1e-30f)));
    float rx = (Q > 0.0f) ? sqrtf(Q * a) * 1.001f : -1.0f;  // 1.001: half-round pad
    float ry = (Q > 0.0f) ? sqrtf(Q * c) * 1.001f : -1.0f;

    float sr = 1.0f / (1.0f + __expf(-rgb[3*i+0]));
    float sg = 1.0f / (1.0f + __expf(-rgb[3*i+1]));
    float sb = 1.0f / (1.0f + __expf(-rgb[3*i+2]));

    F2H2 hh; hh.h = __floats2half2_rn(rx, ry);
    unsigned lo = (unsigned)__float2uint_rn(sr * 65535.0f)
                | ((unsigned)__float2uint_rn(sg * 65535.0f) << 16);
    unsigned hi = (unsigned)__float2uint_rn(sb * 65535.0f)
                | ((unsigned)__float2uint_rn(oeff * 65535.0f) << 16);

    dA[i] = make_float4(u, v, ia, ib);
    dB[i] = make_float4(ic, hh.f, __uint_as_float(lo), __uint_as_float(hi));
    // positive float bits are order-isomorphic as uint; idx low bits = unique + stable
    dKey[i] = ((unsigned long long)__float_as_uint(r) << 32) | (unsigned)i;
}

// ---------------- 2. exact rank sort: one warp per gaussian ------------------
__global__ void __launch_bounds__(1024) rank_scatter_kernel() {
    __shared__ unsigned long long sk[NG];
    int tid = threadIdx.x;
    for (int t = tid; t < NG; t += 1024) sk[t] = dKey[t];
    __syncthreads();

    int w = tid >> 5, lane = tid & 31;
    int g = blockIdx.x * 32 + w;          // 64 blocks x 32 warps = 2048
    unsigned long long kg = sk[g];
    int c = 0;
    #pragma unroll 8
    for (int t = lane; t < NG; t += 32) c += (sk[t] < kg) ? 1 : 0;
    c = __reduce_add_sync(0xffffffffu, c);   // exact rank (keys unique)
    if (lane == 0) {
        gA[c] = dA[g];
        gB[c] = dB[g];
    }
}

// ---------------- 3. split-depth tile rasterization --------------------------
// block = (split, tile): composites sorted range [split*512, split*512+512)
// for its 16x8 tile, writes (r,g,b,T) partial per pixel.
__global__ void __launch_bounds__(TPB) rasterize_kernel() {
    int bid   = blockIdx.x;               // 512 blocks
    int split = bid >> 7;                 // /NTILES
    int tile  = bid & (NTILES - 1);
    int tid   = threadIdx.x;
    int wid   = tid >> 5, lane = tid & 31;
    int tx = tile % TILES_X, ty = tile / TILES_X;
    int lx = tid & (TILE_W - 1), ly = tid >> 4;
    int j = tx * TILE_W + lx;
    int i = ty * TILE_H + ly;
    float pxf = ((float)j - 63.5f) * INV_FOCAL;
    float pyf = ((float)i - 63.5f) * INV_FOCAL;

    float x0 = ((float)(tx * TILE_W) - 63.5f) * INV_FOCAL;
    float x1 = ((float)(tx * TILE_W + TILE_W - 1) - 63.5f) * INV_FOCAL;
    float y0 = ((float)(ty * TILE_H) - 63.5f) * INV_FOCAL;
    float y1 = ((float)(ty * TILE_H + TILE_H - 1) - 63.5f) * INV_FOCAL;

    __shared__ float4 shA[TPB];
    __shared__ float2 shB[TPB];
    __shared__ float4 shC[TPB];
    __shared__ int    wcnt[4];

    float T = 1.0f, cr = 0.0f, cg = 0.0f, cb = 0.0f;

    int kbeg = split * SPLIT_LEN;
    int kend = kbeg + SPLIT_LEN;

    float4 A = gA[kbeg + tid];            // chunk-0 prefetch
    float4 B = gB[kbeg + tid];

    for (int k0 = kbeg; k0 < kend; k0 += TPB) {
        // prefetch next chunk (pad region zero => rr.x = 0 => no hit; safe)
        float4 An = gA[k0 + TPB + tid];
        float4 Bn = gB[k0 + TPB + tid];

        F2H2 hh; hh.f = B.y;
        float2 rr = __half22float2(hh.h);
        bool hit = (rr.x > 0.0f) &&
                   (A.x + rr.x >= x0) && (A.x - rr.x <= x1) &&
                   (A.y + rr.y >= y0) && (A.y - rr.y <= y1);

        unsigned m = __ballot_sync(0xffffffffu, hit);
        if (lane == 0) wcnt[wid] = __popc(m);
        __syncthreads();

        int base = 0, mm = 0;
        #pragma unroll
        for (int w = 0; w < 4; w++) {
            int c = wcnt[w];
            if (w < wid) base += c;
            mm += c;
        }
        if (hit) {
            int off = base + __popc(m & ((1u << lane) - 1u));
            unsigned lo = __float_as_uint(B.z), hi = __float_as_uint(B.w);
            shA[off] = A;
            shB[off] = make_float2(B.x, (float)(hi >> 16) * UNORM_INV);
            shC[off] = make_float4((float)(lo & 0xffffu) * UNORM_INV,
                                   (float)(lo >> 16)     * UNORM_INV,
                                   (float)(hi & 0xffffu) * UNORM_INV, 0.0f);
        }
        __syncthreads();

        #pragma unroll 4
        for (int t = 0; t < mm; t++) {
            float4 Ai = shA[t];
            float2 Bi = shB[t];
            float4 Ci = shC[t];
            float dx = pxf - Ai.x;
            float dy = pyf - Ai.y;
            float e1 = fmaf(Ai.z, dx, Ai.w * dy);
            float e2 = fmaf(Ai.w, dx, Bi.x * dy);
            float qf = fmaf(dx, e1, dy * e2);       // = -0.5*log2e * quadform
            float al = fminf(Bi.y * ex2_approx(qf), 0.99f);
            float w  = T * al;
            cr = fmaf(w, Ci.x, cr);
            cg = fmaf(w, Ci.y, cg);
            cb = fmaf(w, Ci.z, cb);
            T  = fmaf(-al, T, T);
        }
        if (__syncthreads_and(T < 1e-7f)) break;   // segment opaque: rest is moot

        A = An; B = Bn;
    }

    dPart[split][i * IMG_W + j] = make_float4(cr, cg, cb, T);
}

// ---------------- 4. merge the 4 depth-split partials ------------------------
// out = c0 + T0*c1 + T0*T1*c2 + T0*T1*T2*c3
__global__ void __launch_bounds__(128) merge_kernel(float* __restrict__ out) {
    int p = blockIdx.x * blockDim.x + threadIdx.x;   // 128 x 128 = 16384
    float4 p0 = dPart[0][p];
    float4 p1 = dPart[1][p];
    float4 p2 = dPart[2][p];
    float4 p3 = dPart[3][p];
    float T0 = p0.w, T01 = T0 * p1.w, T012 = T01 * p2.w;
    out[3*p+0] = p0.x + T0*p1.x + T01*p2.x + T012*p3.x;
    out[3*p+1] = p0.y + T0*p1.y + T01*p2.y + T012*p3.y;
    out[3*p+2] = p0.z + T0*p1.z + T01*p2.z + T012*p3.z;
}

// ---------------- launch -----------------------------------------------------
extern "C" void kernel_launch(void* const* d_in, const int* in_sizes, int n_in,
                              void* d_out, int out_size) {
    const float* pos   = (const float*)d_in[0];
    const float* rgb   = (const float*)d_in[1];
    const float* opa   = (const float*)d_in[2];
    const float* quat  = (const float*)d_in[3];
    const float* scale = (const float*)d_in[4];
    const float* rot   = (const float*)d_in[5];
    const float* tran  = (const float*)d_in[6];
    float* out = (float*)d_out;

    prep_kernel<<<NG / 128, 128>>>(pos, rgb, opa, quat, scale, rot, tran);
    rank_scatter_kernel<<<NG / 32, 1024>>>();
    rasterize_kernel<<<NTILES * NSPLIT, TPB>>>();
    merge_kernel<<<NPIX / 128, 128>>>(out);
}